// round 15
// baseline (speedup 1.0000x reference)
#include <cuda_runtime.h>
#include <cuda_bf16.h>
#include <cuda_fp16.h>
#include <cstdint>
#include <cstddef>

#define NN   8192
#define DF   784
#define DFP  800     // padded K (25 * 32)
#define DEMB 256
#define TK   11
#define TK2  24      // coarse candidate count (margin >> coarse error)
#define NCB  64      // column blocks per row (NN / 128)
#define WCAP 320     // per-warp survivor capacity
#define NTILES 2080  // upper-triangle 128x128 tiles: 64*65/2

// ---------------- scratch (static device globals; no allocs) ----------------
__device__ float g_sq[NN];                            // correctly-rounded fp32 row norms
__device__ __align__(16) __nv_bfloat16 g_Xb[(size_t)NN * DFP];  // bf16 X, zero-padded
__device__ __align__(16) __half g_D[(size_t)NN * NN]; // fp16 coarse dist (128 MB)
__device__ float g_bmin[(size_t)NN * NCB];            // per-(row, colblock) min (fp16-rounded)
__device__ int   g_idx24[NN * TK2];                   // coarse candidates
__device__ int   g_idx[NN * TK];                      // refined top-11
__device__ int   g_cnt[NN];
__device__ float g_dv[NN];
__device__ float g_G[(size_t)NN * DF];                // gathered dv-weighted rows

__device__ __forceinline__ unsigned smem_u32(const void* p) {
    return (unsigned)__cvta_generic_to_shared(p);
}

// ---------------- 0. convert X -> bf16 (zero-pad K to 800) ----------------
__global__ void conv_kernel(const float* __restrict__ X) {
    int row = blockIdx.x;
    for (int c = threadIdx.x; c < DFP; c += 256) {
        g_Xb[(size_t)row * DFP + c] =
            (c < DF) ? __float2bfloat16_rn(X[(size_t)row * DF + c]) : __float2bfloat16_rn(0.f);
    }
}

// ---------------- 1. row squared norms (correctly rounded) ----------------
__global__ void sq_kernel(const float* __restrict__ X) {
    int row  = blockIdx.x * 8 + (threadIdx.x >> 5);
    int lane = threadIdx.x & 31;
    const float* xr = X + (size_t)row * DF;
    float s = 0.f, c = 0.f;
    for (int k = lane; k < DF; k += 32) {
        float v = xr[k];
        float p = __fmul_rn(v, v);
        float y = __fsub_rn(p, c);
        float t = __fadd_rn(s, y);
        c = __fsub_rn(__fsub_rn(t, s), y);
        s = t;
    }
    double d = (double)s + (double)c;
    #pragma unroll
    for (int o = 16; o; o >>= 1) d += __shfl_xor_sync(0xffffffffu, d, o);
    if (lane == 0) g_sq[row] = (float)d;
}

// ---------------- 2. coarse dist: upper-triangle HMMA + fp16 store + mirror ----------------
#define SROW 40           // smem row stride in bf16 elems (80 B, conflict-free ldmatrix)
#define TPAD 129          // transpose tile stride in halfs (odd -> conflict-free)
#define DSMEM (128 * TPAD * 2 > 2 * 128 * SROW * 2 ? 128 * TPAD * 2 : 2 * 128 * SROW * 2)

__global__ __launch_bounds__(256) void dist_mma() {
    extern __shared__ char dsm[];
    __nv_bfloat16* As = (__nv_bfloat16*)dsm;          // 128*SROW*2 = 10240 B
    __nv_bfloat16* Bs = As + 128 * SROW;              // +10240 B
    __half* tileh = (__half*)dsm;                     // reused for transpose (33024 B)
    __shared__ float swm[128][4];
    __shared__ float scm[128][2];

    // linear block id -> upper-triangle (by, bx), bx >= by
    int t = blockIdx.x;
    int by = (int)(64.5f - sqrtf(64.5f * 64.5f - 2.0f * (float)t));
    while ((by + 1) * 64 - ((by + 1) * by) / 2 <= t) by++;
    while (by * 64 - (by * (by - 1)) / 2 > t) by--;
    int bx = by + (t - (by * 64 - (by * (by - 1)) / 2));

    int tid  = threadIdx.x;
    int warp = tid >> 5, lane = tid & 31;
    int bi = by * 128, bj = bx * 128;
    int wm = (warp >> 2) * 64;     // 0 / 64
    int wn = (warp & 3) * 32;      // 0 / 32 / 64 / 96
    bool offdiag = (bi != bj);

    float acc[4][4][4];
    #pragma unroll
    for (int m = 0; m < 4; m++)
        #pragma unroll
        for (int n = 0; n < 4; n++)
            #pragma unroll
            for (int r = 0; r < 4; r++) acc[m][n][r] = 0.f;

    for (int kt = 0; kt < DFP / 32; kt++) {
        #pragma unroll
        for (int l = 0; l < 2; l++) {
            int q = tid + l * 256;
            int row = q >> 2, ch = q & 3;
            const int4* sa = (const int4*)(g_Xb + (size_t)(bi + row) * DFP + kt * 32 + ch * 8);
            *(int4*)(As + row * SROW + ch * 8) = *sa;
            const int4* sb = (const int4*)(g_Xb + (size_t)(bj + row) * DFP + kt * 32 + ch * 8);
            *(int4*)(Bs + row * SROW + ch * 8) = *sb;
        }
        __syncthreads();

        #pragma unroll
        for (int ks = 0; ks < 2; ks++) {
            int k0 = ks * 16;
            uint32_t a[4][4];
            #pragma unroll
            for (int mt = 0; mt < 4; mt++) {
                unsigned ad = smem_u32(As + (wm + mt * 16 + (lane & 15)) * SROW
                                          + k0 + ((lane >> 4) << 3));
                asm volatile("ldmatrix.sync.aligned.m8n8.x4.shared.b16 {%0,%1,%2,%3}, [%4];"
                             : "=r"(a[mt][0]), "=r"(a[mt][1]), "=r"(a[mt][2]), "=r"(a[mt][3])
                             : "r"(ad));
            }
            uint32_t b[4][2];
            #pragma unroll
            for (int bt = 0; bt < 2; bt++) {
                int nloc = wn + bt * 16 + ((lane >> 4) << 3) + (lane & 7);
                unsigned ad = smem_u32(Bs + nloc * SROW + k0 + (((lane >> 3) & 1) << 3));
                uint32_t r0, r1, r2, r3;
                asm volatile("ldmatrix.sync.aligned.m8n8.x4.shared.b16 {%0,%1,%2,%3}, [%4];"
                             : "=r"(r0), "=r"(r1), "=r"(r2), "=r"(r3) : "r"(ad));
                b[2 * bt][0] = r0; b[2 * bt][1] = r1;
                b[2 * bt + 1][0] = r2; b[2 * bt + 1][1] = r3;
            }
            #pragma unroll
            for (int mt = 0; mt < 4; mt++)
                #pragma unroll
                for (int nt = 0; nt < 4; nt++) {
                    asm volatile(
                        "mma.sync.aligned.m16n8k16.row.col.f32.bf16.bf16.f32 "
                        "{%0,%1,%2,%3}, {%4,%5,%6,%7}, {%8,%9}, {%0,%1,%2,%3};"
                        : "+f"(acc[mt][nt][0]), "+f"(acc[mt][nt][1]),
                          "+f"(acc[mt][nt][2]), "+f"(acc[mt][nt][3])
                        : "r"(a[mt][0]), "r"(a[mt][1]), "r"(a[mt][2]), "r"(a[mt][3]),
                          "r"(b[nt][0]), "r"(b[nt][1]));
                }
        }
        __syncthreads();
    }

    // epilogue: fp16 dist store + row-min over fp16-rounded values
    int r_in = lane >> 2, cb = (lane & 3) * 2;
    #pragma unroll
    for (int mt = 0; mt < 4; mt++) {
        #pragma unroll
        for (int half_ = 0; half_ < 2; half_++) {
            int rloc = wm + mt * 16 + r_in + half_ * 8;
            int gi = bi + rloc;
            float sqi = g_sq[gi];
            float rmin = 3.4e38f;
            #pragma unroll
            for (int nt = 0; nt < 4; nt++) {
                int cloc = wn + nt * 8 + cb;
                int gj = bj + cloc;
                float ox = fabsf(sqi + g_sq[gj]     - 2.f * acc[mt][nt][half_ * 2 + 0]);
                float oy = fabsf(sqi + g_sq[gj + 1] - 2.f * acc[mt][nt][half_ * 2 + 1]);
                __half2 h2 = __floats2half2_rn(ox, oy);
                *reinterpret_cast<__half2*>(g_D + (size_t)gi * NN + gj) = h2;
                float lx = __low2float(h2), ly = __high2float(h2);
                acc[mt][nt][half_ * 2 + 0] = lx;
                acc[mt][nt][half_ * 2 + 1] = ly;
                rmin = fminf(rmin, fminf(lx, ly));
            }
            rmin = fminf(rmin, __shfl_xor_sync(0xffffffffu, rmin, 1));
            rmin = fminf(rmin, __shfl_xor_sync(0xffffffffu, rmin, 2));
            if ((lane & 3) == 0)
                swm[rloc][warp & 3] = rmin;
        }
    }

    if (offdiag) {
        // col-min (mirror-row min) over fp16-rounded values
        #pragma unroll
        for (int nt = 0; nt < 4; nt++) {
            float v0 = 3.4e38f, v1 = 3.4e38f;
            #pragma unroll
            for (int mt = 0; mt < 4; mt++) {
                v0 = fminf(v0, fminf(acc[mt][nt][0], acc[mt][nt][2]));
                v1 = fminf(v1, fminf(acc[mt][nt][1], acc[mt][nt][3]));
            }
            #pragma unroll
            for (int o = 4; o <= 16; o <<= 1) {
                v0 = fminf(v0, __shfl_xor_sync(0xffffffffu, v0, o));
                v1 = fminf(v1, __shfl_xor_sync(0xffffffffu, v1, o));
            }
            if (r_in == 0) {
                scm[wn + nt * 8 + cb + 0][wm >> 6] = v0;
                scm[wn + nt * 8 + cb + 1][wm >> 6] = v1;
            }
        }
        // stage tile (half) for transposed mirror store
        #pragma unroll
        for (int mt = 0; mt < 4; mt++)
            #pragma unroll
            for (int half_ = 0; half_ < 2; half_++) {
                int rloc = wm + mt * 16 + r_in + half_ * 8;
                #pragma unroll
                for (int nt = 0; nt < 4; nt++) {
                    int cloc = wn + nt * 8 + cb;
                    tileh[rloc * TPAD + cloc]     = __float2half_rn(acc[mt][nt][half_ * 2 + 0]);
                    tileh[rloc * TPAD + cloc + 1] = __float2half_rn(acc[mt][nt][half_ * 2 + 1]);
                }
            }
    }
    __syncthreads();

    if (tid < 128) {
        float m = fminf(fminf(swm[tid][0], swm[tid][1]),
                        fminf(swm[tid][2], swm[tid][3]));
        g_bmin[(size_t)(bi + tid) * NCB + bx] = m;
        if (offdiag) {
            float c = fminf(scm[tid][0], scm[tid][1]);
            g_bmin[(size_t)(bj + tid) * NCB + by] = c;
        }
    }

    if (offdiag) {
        // mirror store: D[bj + r][bi + 2c2 .. +1] = (tile[2c2][r], tile[2c2+1][r])
        for (int idx = tid; idx < 128 * 64; idx += 256) {
            int r = idx >> 6, c2 = idx & 63;
            __half a = tileh[(2 * c2) * TPAD + r];
            __half b = tileh[(2 * c2 + 1) * TPAD + r];
            *reinterpret_cast<__half2*>(g_D + (size_t)(bj + r) * NN + bi + 2 * c2) =
                __halves2half2(a, b);
        }
    }
}

// ---------------- 3. per-row top-24, warp-autonomous (one warp per row) ----------------
__global__ __launch_bounds__(256) void topk_fast() {
    int warp = threadIdx.x >> 5, lane = threadIdx.x & 31;
    int row = blockIdx.x * 8 + warp;

    __shared__ float sbm[8][NCB];
    __shared__ unsigned long long wbuf[8][WCAP];
    __shared__ int wcnt[8];

    // load this row's 64 block-mins (2 per lane)
    float b0 = g_bmin[(size_t)row * NCB + lane];
    float b1 = g_bmin[(size_t)row * NCB + lane + 32];
    sbm[warp][lane]      = b0;
    sbm[warp][lane + 32] = b1;
    if (lane == 0) wcnt[warp] = 0;
    __syncwarp();

    // rank-select T = 24th smallest (strict order via index tiebreak)
    int r0 = 0, r1 = 0;
    #pragma unroll
    for (int j = 0; j < NCB; j++) {
        float y = sbm[warp][j];
        r0 += (y < b0) || (y == b0 && j < lane);
        r1 += (y < b1) || (y == b1 && j < lane + 32);
    }
    float myT = (r0 == TK2 - 1) ? b0 : ((r1 == TK2 - 1) ? b1 : -1.f);
    #pragma unroll
    for (int o = 16; o; o >>= 1) myT = fmaxf(myT, __shfl_xor_sync(0xffffffffu, myT, o));
    float T = myT;                                    // distances >= 0, sentinel -1 safe
    __half2 T2 = __half2half2(__float2half_rn(T));    // T is an fp16-stored value: exact

    // filter: 32 uint4/lane in 4 batches of MLP=8
    const uint4* dr4 = (const uint4*)(g_D + (size_t)row * NN);
    #pragma unroll
    for (int g = 0; g < 4; g++) {
        uint4 w[8];
        #pragma unroll
        for (int i = 0; i < 8; i++) w[i] = dr4[lane + (g * 8 + i) * 32];
        #pragma unroll
        for (int i = 0; i < 8; i++) {
            int base = (lane + (g * 8 + i) * 32) * 8;
            const __half2* hp = (const __half2*)&w[i];
            #pragma unroll
            for (int q = 0; q < 4; q++) {
                __half2 h = hp[q];
                if (!__hbgt2(h, T2)) {    // at least one lane <= T (rare)
                    float fx = __low2float(h), fy = __high2float(h);
                    if (fx <= T) {
                        int p = atomicAdd(&wcnt[warp], 1);
                        if (p < WCAP)
                            wbuf[warp][p] =
                                ((unsigned long long)__float_as_uint(fx) << 32)
                                | (unsigned)(base + 2 * q);
                    }
                    if (fy <= T) {
                        int p = atomicAdd(&wcnt[warp], 1);
                        if (p < WCAP)
                            wbuf[warp][p] =
                                ((unsigned long long)__float_as_uint(fy) << 32)
                                | (unsigned)(base + 2 * q + 1);
                    }
                }
            }
        }
    }
    __syncwarp();

    if (lane == 0) {
        int n = wcnt[warp];
        unsigned long long best[TK2];
        #pragma unroll
        for (int k = 0; k < TK2; k++) best[k] = ~0ull;
        if (n <= WCAP) {
            for (int i = 0; i < n; i++) {
                unsigned long long x = wbuf[warp][i];
                if (x < best[TK2 - 1]) {
                    int k = TK2 - 1;
                    while (k > 0 && best[k - 1] > x) { best[k] = best[k - 1]; k--; }
                    best[k] = x;
                }
            }
        } else {
            // fallback (practically unreachable): full serial scan of fp16 row
            const __half* drh = g_D + (size_t)row * NN;
            for (int j = 0; j < NN; j++) {
                float d = __half2float(drh[j]);
                unsigned long long x =
                    ((unsigned long long)__float_as_uint(d) << 32) | (unsigned)j;
                if (x < best[TK2 - 1]) {
                    int k = TK2 - 1;
                    while (k > 0 && best[k - 1] > x) { best[k] = best[k - 1]; k--; }
                    best[k] = x;
                }
            }
        }
        #pragma unroll
        for (int k = 0; k < TK2; k++) g_idx24[row * TK2 + k] = (int)(unsigned)best[k];
    }
}

// ---------------- 4. refine: exact dists with ref's rounding chain, pick top-11 ----------------
__global__ __launch_bounds__(128) void refine_kernel(const float* __restrict__ X) {
    int row = blockIdx.x;
    int wid = threadIdx.x >> 5, lane = threadIdx.x & 31;
    __shared__ unsigned long long keys[TK2];
    __shared__ int cand[TK2];
    if (threadIdx.x < TK2) cand[threadIdx.x] = g_idx24[row * TK2 + threadIdx.x];
    __syncthreads();

    float sqi = g_sq[row];
    const float* xi = X + (size_t)row * DF;

    for (int k4 = wid; k4 < TK2; k4 += 4) {
        int j = cand[k4];
        const float* xj = X + (size_t)j * DF;
        float s = 0.f, c = 0.f;
        for (int k = lane; k < DF; k += 32) {
            float p = __fmul_rn(xi[k], xj[k]);
            float y = __fsub_rn(p, c);
            float t = __fadd_rn(s, y);
            c = __fsub_rn(__fsub_rn(t, s), y);
            s = t;
        }
        double d = (double)s + (double)c;
        #pragma unroll
        for (int o = 16; o; o >>= 1) d += __shfl_xor_sync(0xffffffffu, d, o);
        if (lane == 0) {
            float dotf = (float)d;
            float t1 = __fadd_rn(sqi, g_sq[j]);
            float t3 = fabsf(__fsub_rn(t1, __fmul_rn(2.0f, dotf)));
            keys[k4] = ((unsigned long long)__float_as_uint(t3) << 32) | (unsigned)j;
        }
    }
    __syncthreads();

    if (threadIdx.x == 0) {
        unsigned long long a[TK2];
        #pragma unroll
        for (int i = 0; i < TK2; i++) a[i] = keys[i];
        #pragma unroll
        for (int i = 1; i < TK2; i++) {
            unsigned long long v = a[i];
            int k = i - 1;
            while (k >= 0 && a[k] > v) { a[k + 1] = a[k]; k--; }
            a[k + 1] = v;
        }
        #pragma unroll
        for (int k = 0; k < TK; k++) g_idx[row * TK + k] = (int)(unsigned)a[k];
    }
}

// ---------------- 5. vertex degrees ----------------
__global__ void zero_cnt() {
    int t = blockIdx.x * 256 + threadIdx.x;
    if (t < NN) g_cnt[t] = 0;
}
__global__ void count_kernel() {
    int t = blockIdx.x * 256 + threadIdx.x;
    if (t < NN * TK) atomicAdd(&g_cnt[g_idx[t]], 1);
}
__global__ void dv_kernel() {
    int t = blockIdx.x * 256 + threadIdx.x;
    if (t < NN) g_dv[t] = 1.0f / sqrtf((float)g_cnt[t]);
}

// ---------------- zero fill ----------------
__global__ void zero_kernel(float4* __restrict__ p, size_t n4) {
    size_t t = (size_t)blockIdx.x * blockDim.x + threadIdx.x;
    size_t stride = (size_t)gridDim.x * blockDim.x;
    float4 z = make_float4(0.f, 0.f, 0.f, 0.f);
    for (size_t i = t; i < n4; i += stride) p[i] = z;
}

// ---------------- 6. H scatter: H[idx[i][k]][i] = 1 ----------------
__global__ void scatterH(float* __restrict__ H) {
    int t = blockIdx.x * 256 + threadIdx.x;
    if (t < NN * TK) {
        int i = t / TK;
        int r = g_idx[t];
        H[(size_t)r * NN + i] = 1.0f;
    }
}

// ---------------- 7. gather: G[i] = sum_k dv[idx]*X[idx] ----------------
__global__ __launch_bounds__(256) void gather_kernel(const float* __restrict__ X) {
    int i = blockIdx.x;
    __shared__ int   sidx[TK];
    __shared__ float sdv[TK];
    if (threadIdx.x < TK) {
        int r = g_idx[i * TK + threadIdx.x];
        sidx[threadIdx.x] = r;
        sdv[threadIdx.x]  = g_dv[r];
    }
    __syncthreads();
    for (int c = threadIdx.x; c < DF; c += 256) {
        float s = 0.f;
        #pragma unroll
        for (int k = 0; k < TK; k++)
            s = fmaf(sdv[k], X[(size_t)sidx[k] * DF + c], s);
        g_G[(size_t)i * DF + c] = s;
    }
}

// ---------------- 8. X_out = de * G @ theta   (M=8192, N=256, K=784) ----------------
#define BK 16
#define SPAD 4
__global__ __launch_bounds__(256) void out_gemm(const float* __restrict__ theta,
                                                float* __restrict__ Xout) {
    __shared__ float As[BK][64 + SPAD];
    __shared__ float Bs[BK][64 + SPAD];
    int tid = threadIdx.x;
    int tx = tid & 15, ty = tid >> 4;
    int bi = blockIdx.y * 64, bj = blockIdx.x * 64;

    float acc[4][4];
    #pragma unroll
    for (int m = 0; m < 4; m++)
        #pragma unroll
        for (int n = 0; n < 4; n++) acc[m][n] = 0.f;

    for (int k0 = 0; k0 < DF; k0 += BK) {
        {
            int row = tid >> 2, c4 = (tid & 3) * 4;
            float4 v = *reinterpret_cast<const float4*>(g_G + (size_t)(bi + row) * DF + k0 + c4);
            As[c4 + 0][row] = v.x; As[c4 + 1][row] = v.y;
            As[c4 + 2][row] = v.z; As[c4 + 3][row] = v.w;
            int kr = tid >> 4, n4 = (tid & 15) * 4;
            float4 w = *reinterpret_cast<const float4*>(theta + (size_t)(k0 + kr) * DEMB + bj + n4);
            Bs[kr][n4 + 0] = w.x; Bs[kr][n4 + 1] = w.y;
            Bs[kr][n4 + 2] = w.z; Bs[kr][n4 + 3] = w.w;
        }
        __syncthreads();
        #pragma unroll
        for (int kk = 0; kk < BK; kk++) {
            float a[4], b[4];
            #pragma unroll
            for (int m = 0; m < 4; m++) a[m] = As[kk][ty * 4 + m];
            #pragma unroll
            for (int n = 0; n < 4; n++) b[n] = Bs[kk][tx * 4 + n];
            #pragma unroll
            for (int m = 0; m < 4; m++)
                #pragma unroll
                for (int n = 0; n < 4; n++) acc[m][n] = fmaf(a[m], b[n], acc[m][n]);
        }
        __syncthreads();
    }
    const float de = 0.30151134457776363f;  // 11^-0.5
    #pragma unroll
    for (int m = 0; m < 4; m++) {
        int i = bi + ty * 4 + m;
        float4 o;
        o.x = de * acc[m][0]; o.y = de * acc[m][1];
        o.z = de * acc[m][2]; o.w = de * acc[m][3];
        *reinterpret_cast<float4*>(Xout + (size_t)i * DEMB + bj + tx * 4) = o;
    }
}

// ---------------- 9. E = dv * de * scatter-add of X_out ----------------
__global__ void scatterE(const float* __restrict__ Xout, float* __restrict__ E) {
    int j = blockIdx.x;
    int c = threadIdx.x;
    float v = Xout[(size_t)j * DEMB + c];
    #pragma unroll
    for (int k = 0; k < TK; k++) {
        int r = __ldg(&g_idx[j * TK + k]);
        atomicAdd(E + (size_t)r * DEMB + c, v);
    }
}
__global__ void scaleE(float* __restrict__ E) {
    int t = blockIdx.x * 256 + threadIdx.x;
    const float de = 0.30151134457776363f;
    int i = t >> 8;
    E[t] *= g_dv[i] * de;
}

// ---------------- launch ----------------
extern "C" void kernel_launch(void* const* d_in, const int* in_sizes, int n_in,
                              void* d_out, int out_size) {
    const float* X     = (const float*)d_in[0];
    const float* theta = (const float*)d_in[1];
    float* out  = (float*)d_out;
    float* Xout = out;                                // [8192, 256]
    float* E    = out + (size_t)NN * DEMB;            // [8192, 256]
    float* H    = out + 2 * (size_t)NN * DEMB;        // [8192, 8192]

    static bool attr_set = false;
    if (!attr_set) {
        cudaFuncSetAttribute(dist_mma, cudaFuncAttributeMaxDynamicSharedMemorySize, DSMEM);
        attr_set = true;
    }

    conv_kernel<<<NN, 256>>>(X);
    sq_kernel<<<NN / 8, 256>>>(X);
    dist_mma<<<NTILES, 256, DSMEM>>>();               // upper-tri HMMA -> fp16 D + mirror
    topk_fast<<<NN / 8, 256>>>();                     // warp-per-row threshold filter
    refine_kernel<<<NN, 128>>>(X);                    // exact-emulated top-11
    zero_cnt<<<NN / 256, 256>>>();
    count_kernel<<<(NN * TK + 255) / 256, 256>>>();
    dv_kernel<<<NN / 256, 256>>>();
    zero_kernel<<<2048, 256>>>((float4*)H, (size_t)NN * NN / 4);
    scatterH<<<(NN * TK + 255) / 256, 256>>>(H);
    gather_kernel<<<NN, 256>>>(X);
    out_gemm<<<dim3(DEMB / 64, NN / 64), 256>>>(theta, Xout);
    zero_kernel<<<256, 256>>>((float4*)E, (size_t)NN * DEMB / 4);
    scatterE<<<NN, 256>>>(Xout, E);
    scaleE<<<NN * DEMB / 256, 256>>>(E);
}

// round 16
// speedup vs baseline: 1.0222x; 1.0222x over previous
#include <cuda_runtime.h>
#include <cuda_bf16.h>
#include <cuda_fp16.h>
#include <cstdint>
#include <cstddef>

#define NN   8192
#define DF   784
#define DFP  800     // padded K (25 * 32)
#define DEMB 256
#define TK   11
#define TK2  24      // coarse candidate count (margin >> coarse error)
#define NCB  64      // column blocks per row (NN / 128)
#define CAP  512     // survivor buffer capacity
#define NTILES 2080  // upper-triangle 128x128 tiles: 64*65/2

// ---------------- scratch (static device globals; no allocs) ----------------
__device__ float g_sq[NN];                            // correctly-rounded fp32 row norms
__device__ __align__(16) __nv_bfloat16 g_Xb[(size_t)NN * DFP];  // bf16 X, zero-padded
__device__ __align__(16) __half g_D[(size_t)NN * NN]; // fp16 coarse dist (128 MB)
__device__ float g_bmin[(size_t)NN * NCB];            // per-(row, colblock) min (fp16-rounded)
__device__ int   g_idx24[NN * TK2];                   // coarse candidates
__device__ int   g_idx[NN * TK];                      // refined top-11
__device__ int   g_cnt[NN];
__device__ float g_dv[NN];
__device__ float g_G[(size_t)NN * DF];                // gathered dv-weighted rows

__device__ __forceinline__ unsigned smem_u32(const void* p) {
    return (unsigned)__cvta_generic_to_shared(p);
}

// ---------------- 0. convert X -> bf16 (zero-pad K to 800) ----------------
__global__ void conv_kernel(const float* __restrict__ X) {
    int row = blockIdx.x;
    for (int c = threadIdx.x; c < DFP; c += 256) {
        g_Xb[(size_t)row * DFP + c] =
            (c < DF) ? __float2bfloat16_rn(X[(size_t)row * DF + c]) : __float2bfloat16_rn(0.f);
    }
}

// ---------------- 1. row squared norms (correctly rounded) ----------------
__global__ void sq_kernel(const float* __restrict__ X) {
    int row  = blockIdx.x * 8 + (threadIdx.x >> 5);
    int lane = threadIdx.x & 31;
    const float* xr = X + (size_t)row * DF;
    float s = 0.f, c = 0.f;
    for (int k = lane; k < DF; k += 32) {
        float v = xr[k];
        float p = __fmul_rn(v, v);
        float y = __fsub_rn(p, c);
        float t = __fadd_rn(s, y);
        c = __fsub_rn(__fsub_rn(t, s), y);
        s = t;
    }
    double d = (double)s + (double)c;
    #pragma unroll
    for (int o = 16; o; o >>= 1) d += __shfl_xor_sync(0xffffffffu, d, o);
    if (lane == 0) g_sq[row] = (float)d;
}

// ---------------- 2. coarse dist: upper-triangle HMMA + fp16 store + mirror ----------------
#define SROW 40           // smem row stride in bf16 elems (80 B, conflict-free ldmatrix)
#define TPAD 129          // transpose tile stride in halfs (odd -> conflict-free)
#define DSMEM (128 * TPAD * 2 > 2 * 128 * SROW * 2 ? 128 * TPAD * 2 : 2 * 128 * SROW * 2)

__global__ __launch_bounds__(256) void dist_mma() {
    extern __shared__ char dsm[];
    __nv_bfloat16* As = (__nv_bfloat16*)dsm;          // 128*SROW*2 = 10240 B
    __nv_bfloat16* Bs = As + 128 * SROW;              // +10240 B
    __half* tileh = (__half*)dsm;                     // reused for transpose (33024 B)
    __shared__ float swm[128][4];
    __shared__ float scm[128][2];

    // linear block id -> upper-triangle (by, bx), bx >= by
    int t = blockIdx.x;
    int by = (int)(64.5f - sqrtf(64.5f * 64.5f - 2.0f * (float)t));
    while ((by + 1) * 64 - ((by + 1) * by) / 2 <= t) by++;
    while (by * 64 - (by * (by - 1)) / 2 > t) by--;
    int bx = by + (t - (by * 64 - (by * (by - 1)) / 2));

    int tid  = threadIdx.x;
    int warp = tid >> 5, lane = tid & 31;
    int bi = by * 128, bj = bx * 128;
    int wm = (warp >> 2) * 64;     // 0 / 64
    int wn = (warp & 3) * 32;      // 0 / 32 / 64 / 96
    bool offdiag = (bi != bj);

    float acc[4][4][4];
    #pragma unroll
    for (int m = 0; m < 4; m++)
        #pragma unroll
        for (int n = 0; n < 4; n++)
            #pragma unroll
            for (int r = 0; r < 4; r++) acc[m][n][r] = 0.f;

    for (int kt = 0; kt < DFP / 32; kt++) {
        #pragma unroll
        for (int l = 0; l < 2; l++) {
            int q = tid + l * 256;
            int row = q >> 2, ch = q & 3;
            const int4* sa = (const int4*)(g_Xb + (size_t)(bi + row) * DFP + kt * 32 + ch * 8);
            *(int4*)(As + row * SROW + ch * 8) = *sa;
            const int4* sb = (const int4*)(g_Xb + (size_t)(bj + row) * DFP + kt * 32 + ch * 8);
            *(int4*)(Bs + row * SROW + ch * 8) = *sb;
        }
        __syncthreads();

        #pragma unroll
        for (int ks = 0; ks < 2; ks++) {
            int k0 = ks * 16;
            uint32_t a[4][4];
            #pragma unroll
            for (int mt = 0; mt < 4; mt++) {
                unsigned ad = smem_u32(As + (wm + mt * 16 + (lane & 15)) * SROW
                                          + k0 + ((lane >> 4) << 3));
                asm volatile("ldmatrix.sync.aligned.m8n8.x4.shared.b16 {%0,%1,%2,%3}, [%4];"
                             : "=r"(a[mt][0]), "=r"(a[mt][1]), "=r"(a[mt][2]), "=r"(a[mt][3])
                             : "r"(ad));
            }
            uint32_t b[4][2];
            #pragma unroll
            for (int bt = 0; bt < 2; bt++) {
                int nloc = wn + bt * 16 + ((lane >> 4) << 3) + (lane & 7);
                unsigned ad = smem_u32(Bs + nloc * SROW + k0 + (((lane >> 3) & 1) << 3));
                uint32_t r0, r1, r2, r3;
                asm volatile("ldmatrix.sync.aligned.m8n8.x4.shared.b16 {%0,%1,%2,%3}, [%4];"
                             : "=r"(r0), "=r"(r1), "=r"(r2), "=r"(r3) : "r"(ad));
                b[2 * bt][0] = r0; b[2 * bt][1] = r1;
                b[2 * bt + 1][0] = r2; b[2 * bt + 1][1] = r3;
            }
            #pragma unroll
            for (int mt = 0; mt < 4; mt++)
                #pragma unroll
                for (int nt = 0; nt < 4; nt++) {
                    asm volatile(
                        "mma.sync.aligned.m16n8k16.row.col.f32.bf16.bf16.f32 "
                        "{%0,%1,%2,%3}, {%4,%5,%6,%7}, {%8,%9}, {%0,%1,%2,%3};"
                        : "+f"(acc[mt][nt][0]), "+f"(acc[mt][nt][1]),
                          "+f"(acc[mt][nt][2]), "+f"(acc[mt][nt][3])
                        : "r"(a[mt][0]), "r"(a[mt][1]), "r"(a[mt][2]), "r"(a[mt][3]),
                          "r"(b[nt][0]), "r"(b[nt][1]));
                }
        }
        __syncthreads();
    }

    // epilogue: fp16 dist store + row-min over fp16-rounded values
    int r_in = lane >> 2, cb = (lane & 3) * 2;
    #pragma unroll
    for (int mt = 0; mt < 4; mt++) {
        #pragma unroll
        for (int half_ = 0; half_ < 2; half_++) {
            int rloc = wm + mt * 16 + r_in + half_ * 8;
            int gi = bi + rloc;
            float sqi = g_sq[gi];
            float rmin = 3.4e38f;
            #pragma unroll
            for (int nt = 0; nt < 4; nt++) {
                int cloc = wn + nt * 8 + cb;
                int gj = bj + cloc;
                float ox = fabsf(sqi + g_sq[gj]     - 2.f * acc[mt][nt][half_ * 2 + 0]);
                float oy = fabsf(sqi + g_sq[gj + 1] - 2.f * acc[mt][nt][half_ * 2 + 1]);
                __half2 h2 = __floats2half2_rn(ox, oy);
                *reinterpret_cast<__half2*>(g_D + (size_t)gi * NN + gj) = h2;
                float lx = __low2float(h2), ly = __high2float(h2);
                acc[mt][nt][half_ * 2 + 0] = lx;
                acc[mt][nt][half_ * 2 + 1] = ly;
                rmin = fminf(rmin, fminf(lx, ly));
            }
            rmin = fminf(rmin, __shfl_xor_sync(0xffffffffu, rmin, 1));
            rmin = fminf(rmin, __shfl_xor_sync(0xffffffffu, rmin, 2));
            if ((lane & 3) == 0)
                swm[rloc][warp & 3] = rmin;
        }
    }

    if (offdiag) {
        // col-min (mirror-row min) over fp16-rounded values
        #pragma unroll
        for (int nt = 0; nt < 4; nt++) {
            float v0 = 3.4e38f, v1 = 3.4e38f;
            #pragma unroll
            for (int mt = 0; mt < 4; mt++) {
                v0 = fminf(v0, fminf(acc[mt][nt][0], acc[mt][nt][2]));
                v1 = fminf(v1, fminf(acc[mt][nt][1], acc[mt][nt][3]));
            }
            #pragma unroll
            for (int o = 4; o <= 16; o <<= 1) {
                v0 = fminf(v0, __shfl_xor_sync(0xffffffffu, v0, o));
                v1 = fminf(v1, __shfl_xor_sync(0xffffffffu, v1, o));
            }
            if (r_in == 0) {
                scm[wn + nt * 8 + cb + 0][wm >> 6] = v0;
                scm[wn + nt * 8 + cb + 1][wm >> 6] = v1;
            }
        }
        // stage tile (half) for transposed mirror store
        #pragma unroll
        for (int mt = 0; mt < 4; mt++)
            #pragma unroll
            for (int half_ = 0; half_ < 2; half_++) {
                int rloc = wm + mt * 16 + r_in + half_ * 8;
                #pragma unroll
                for (int nt = 0; nt < 4; nt++) {
                    int cloc = wn + nt * 8 + cb;
                    tileh[rloc * TPAD + cloc]     = __float2half_rn(acc[mt][nt][half_ * 2 + 0]);
                    tileh[rloc * TPAD + cloc + 1] = __float2half_rn(acc[mt][nt][half_ * 2 + 1]);
                }
            }
    }
    __syncthreads();

    if (tid < 128) {
        float m = fminf(fminf(swm[tid][0], swm[tid][1]),
                        fminf(swm[tid][2], swm[tid][3]));
        g_bmin[(size_t)(bi + tid) * NCB + bx] = m;
        if (offdiag) {
            float c = fminf(scm[tid][0], scm[tid][1]);
            g_bmin[(size_t)(bj + tid) * NCB + by] = c;
        }
    }

    if (offdiag) {
        // mirror store: D[bj + r][bi + 2c2 .. +1] = (tile[2c2][r], tile[2c2+1][r])
        for (int idx = tid; idx < 128 * 64; idx += 256) {
            int r = idx >> 6, c2 = idx & 63;
            __half a = tileh[(2 * c2) * TPAD + r];
            __half b = tileh[(2 * c2 + 1) * TPAD + r];
            *reinterpret_cast<__half2*>(g_D + (size_t)(bj + r) * NN + bi + 2 * c2) =
                __halves2half2(a, b);
        }
    }
}

// ---------------- 3. per-row top-24 via threshold filter (fp16, MLP=8; R13 config) ----------------
__global__ __launch_bounds__(128) void topk_fast() {
    int row = blockIdx.x, t = threadIdx.x;
    __shared__ float sb[NCB];
    __shared__ float sT;
    __shared__ int cnt;
    __shared__ unsigned long long buf[CAP];

    if (t < NCB) sb[t] = g_bmin[(size_t)row * NCB + t];
    if (t == 0) cnt = 0;
    __syncthreads();

    // parallel rank-select: T = 24th smallest block-min
    if (t < NCB) {
        float x = sb[t];
        int r = 0;
        #pragma unroll 16
        for (int j = 0; j < NCB; j++)
            r += (sb[j] < x) || (sb[j] == x && j < t);
        if (r == TK2 - 1) sT = x;
    }
    __syncthreads();
    float T = sT;
    __half2 T2 = __half2half2(__float2half_rn(T));   // T is fp16-representable exactly

    // preload 8 x uint4 (128 B = 64 halfs / thread): MLP=8
    const uint4* dr4 = (const uint4*)(g_D + (size_t)row * NN);
    uint4 w[8];
    #pragma unroll
    for (int i = 0; i < 8; i++) w[i] = dr4[t + i * 128];

    #pragma unroll
    for (int i = 0; i < 8; i++) {
        int base = (t + i * 128) * 8;    // first half index of this uint4
        const __half2* hp = (const __half2*)&w[i];
        #pragma unroll
        for (int q = 0; q < 4; q++) {
            __half2 h = hp[q];
            if (!__hbgt2(h, T2)) {       // at least one lane <= T (rare)
                float fx = __low2float(h), fy = __high2float(h);
                if (fx <= T) {
                    int p = atomicAdd(&cnt, 1);
                    if (p < CAP)
                        buf[p] = ((unsigned long long)__float_as_uint(fx) << 32)
                                 | (unsigned)(base + 2 * q);
                }
                if (fy <= T) {
                    int p = atomicAdd(&cnt, 1);
                    if (p < CAP)
                        buf[p] = ((unsigned long long)__float_as_uint(fy) << 32)
                                 | (unsigned)(base + 2 * q + 1);
                }
            }
        }
    }
    __syncthreads();

    if (t == 0) {
        unsigned long long best[TK2];
        #pragma unroll
        for (int k = 0; k < TK2; k++) best[k] = ~0ull;
        if (cnt <= CAP) {
            int n = cnt;
            for (int i = 0; i < n; i++) {
                unsigned long long x = buf[i];
                if (x < best[TK2 - 1]) {
                    int k = TK2 - 1;
                    while (k > 0 && best[k - 1] > x) { best[k] = best[k - 1]; k--; }
                    best[k] = x;
                }
            }
        } else {
            // fallback (practically unreachable): full serial scan of fp16 row
            const __half* drh = g_D + (size_t)row * NN;
            for (int j = 0; j < NN; j++) {
                float d = __half2float(drh[j]);
                unsigned long long x =
                    ((unsigned long long)__float_as_uint(d) << 32) | (unsigned)j;
                if (x < best[TK2 - 1]) {
                    int k = TK2 - 1;
                    while (k > 0 && best[k - 1] > x) { best[k] = best[k - 1]; k--; }
                    best[k] = x;
                }
            }
        }
        #pragma unroll
        for (int k = 0; k < TK2; k++) g_idx24[row * TK2 + k] = (int)(unsigned)best[k];
    }
}

// ---------------- 4. refine: one warp per candidate (24 warps/row), exact chain ----------------
__global__ __launch_bounds__(768) void refine_kernel(const float* __restrict__ X) {
    int row = blockIdx.x;
    int wid = threadIdx.x >> 5, lane = threadIdx.x & 31;
    __shared__ unsigned long long keys[TK2];
    __shared__ int cand[TK2];
    if (threadIdx.x < TK2) cand[threadIdx.x] = g_idx24[row * TK2 + threadIdx.x];
    __syncthreads();

    float sqi = g_sq[row];
    const float* xi = X + (size_t)row * DF;

    {
        int j = cand[wid];
        const float* xj = X + (size_t)j * DF;
        float s = 0.f, c = 0.f;
        for (int k = lane; k < DF; k += 32) {
            float p = __fmul_rn(xi[k], xj[k]);
            float y = __fsub_rn(p, c);
            float t = __fadd_rn(s, y);
            c = __fsub_rn(__fsub_rn(t, s), y);
            s = t;
        }
        double d = (double)s + (double)c;
        #pragma unroll
        for (int o = 16; o; o >>= 1) d += __shfl_xor_sync(0xffffffffu, d, o);
        if (lane == 0) {
            float dotf = (float)d;
            float t1 = __fadd_rn(sqi, g_sq[j]);
            float t3 = fabsf(__fsub_rn(t1, __fmul_rn(2.0f, dotf)));
            keys[wid] = ((unsigned long long)__float_as_uint(t3) << 32) | (unsigned)j;
        }
    }
    __syncthreads();

    if (threadIdx.x == 0) {
        unsigned long long a[TK2];
        #pragma unroll
        for (int i = 0; i < TK2; i++) a[i] = keys[i];
        #pragma unroll
        for (int i = 1; i < TK2; i++) {
            unsigned long long v = a[i];
            int k = i - 1;
            while (k >= 0 && a[k] > v) { a[k + 1] = a[k]; k--; }
            a[k + 1] = v;
        }
        #pragma unroll
        for (int k = 0; k < TK; k++) g_idx[row * TK + k] = (int)(unsigned)a[k];
    }
}

// ---------------- 5. vertex degrees ----------------
__global__ void zero_cnt() {
    int t = blockIdx.x * 256 + threadIdx.x;
    if (t < NN) g_cnt[t] = 0;
}
__global__ void count_kernel() {
    int t = blockIdx.x * 256 + threadIdx.x;
    if (t < NN * TK) atomicAdd(&g_cnt[g_idx[t]], 1);
}
__global__ void dv_kernel() {
    int t = blockIdx.x * 256 + threadIdx.x;
    if (t < NN) g_dv[t] = 1.0f / sqrtf((float)g_cnt[t]);
}

// ---------------- zero fill ----------------
__global__ void zero_kernel(float4* __restrict__ p, size_t n4) {
    size_t t = (size_t)blockIdx.x * blockDim.x + threadIdx.x;
    size_t stride = (size_t)gridDim.x * blockDim.x;
    float4 z = make_float4(0.f, 0.f, 0.f, 0.f);
    for (size_t i = t; i < n4; i += stride) p[i] = z;
}

// ---------------- 6. H scatter: H[idx[i][k]][i] = 1 ----------------
__global__ void scatterH(float* __restrict__ H) {
    int t = blockIdx.x * 256 + threadIdx.x;
    if (t < NN * TK) {
        int i = t / TK;
        int r = g_idx[t];
        H[(size_t)r * NN + i] = 1.0f;
    }
}

// ---------------- 7. gather: G[i] = sum_k dv[idx]*X[idx] ----------------
__global__ __launch_bounds__(256) void gather_kernel(const float* __restrict__ X) {
    int i = blockIdx.x;
    __shared__ int   sidx[TK];
    __shared__ float sdv[TK];
    if (threadIdx.x < TK) {
        int r = g_idx[i * TK + threadIdx.x];
        sidx[threadIdx.x] = r;
        sdv[threadIdx.x]  = g_dv[r];
    }
    __syncthreads();
    for (int c = threadIdx.x; c < DF; c += 256) {
        float s = 0.f;
        #pragma unroll
        for (int k = 0; k < TK; k++)
            s = fmaf(sdv[k], X[(size_t)sidx[k] * DF + c], s);
        g_G[(size_t)i * DF + c] = s;
    }
}

// ---------------- 8. X_out = de * G @ theta   (M=8192, N=256, K=784) ----------------
#define BK 16
#define SPAD 4
__global__ __launch_bounds__(256) void out_gemm(const float* __restrict__ theta,
                                                float* __restrict__ Xout) {
    __shared__ float As[BK][64 + SPAD];
    __shared__ float Bs[BK][64 + SPAD];
    int tid = threadIdx.x;
    int tx = tid & 15, ty = tid >> 4;
    int bi = blockIdx.y * 64, bj = blockIdx.x * 64;

    float acc[4][4];
    #pragma unroll
    for (int m = 0; m < 4; m++)
        #pragma unroll
        for (int n = 0; n < 4; n++) acc[m][n] = 0.f;

    for (int k0 = 0; k0 < DF; k0 += BK) {
        {
            int row = tid >> 2, c4 = (tid & 3) * 4;
            float4 v = *reinterpret_cast<const float4*>(g_G + (size_t)(bi + row) * DF + k0 + c4);
            As[c4 + 0][row] = v.x; As[c4 + 1][row] = v.y;
            As[c4 + 2][row] = v.z; As[c4 + 3][row] = v.w;
            int kr = tid >> 4, n4 = (tid & 15) * 4;
            float4 w = *reinterpret_cast<const float4*>(theta + (size_t)(k0 + kr) * DEMB + bj + n4);
            Bs[kr][n4 + 0] = w.x; Bs[kr][n4 + 1] = w.y;
            Bs[kr][n4 + 2] = w.z; Bs[kr][n4 + 3] = w.w;
        }
        __syncthreads();
        #pragma unroll
        for (int kk = 0; kk < BK; kk++) {
            float a[4], b[4];
            #pragma unroll
            for (int m = 0; m < 4; m++) a[m] = As[kk][ty * 4 + m];
            #pragma unroll
            for (int n = 0; n < 4; n++) b[n] = Bs[kk][tx * 4 + n];
            #pragma unroll
            for (int m = 0; m < 4; m++)
                #pragma unroll
                for (int n = 0; n < 4; n++) acc[m][n] = fmaf(a[m], b[n], acc[m][n]);
        }
        __syncthreads();
    }
    const float de = 0.30151134457776363f;  // 11^-0.5
    #pragma unroll
    for (int m = 0; m < 4; m++) {
        int i = bi + ty * 4 + m;
        float4 o;
        o.x = de * acc[m][0]; o.y = de * acc[m][1];
        o.z = de * acc[m][2]; o.w = de * acc[m][3];
        *reinterpret_cast<float4*>(Xout + (size_t)i * DEMB + bj + tx * 4) = o;
    }
}

// ---------------- 9. E = dv * de * scatter-add of X_out ----------------
__global__ void scatterE(const float* __restrict__ Xout, float* __restrict__ E) {
    int j = blockIdx.x;
    int c = threadIdx.x;
    float v = Xout[(size_t)j * DEMB + c];
    #pragma unroll
    for (int k = 0; k < TK; k++) {
        int r = __ldg(&g_idx[j * TK + k]);
        atomicAdd(E + (size_t)r * DEMB + c, v);
    }
}
__global__ void scaleE(float* __restrict__ E) {
    int t = blockIdx.x * 256 + threadIdx.x;
    const float de = 0.30151134457776363f;
    int i = t >> 8;
    E[t] *= g_dv[i] * de;
}

// ---------------- launch ----------------
extern "C" void kernel_launch(void* const* d_in, const int* in_sizes, int n_in,
                              void* d_out, int out_size) {
    const float* X     = (const float*)d_in[0];
    const float* theta = (const float*)d_in[1];
    float* out  = (float*)d_out;
    float* Xout = out;                                // [8192, 256]
    float* E    = out + (size_t)NN * DEMB;            // [8192, 256]
    float* H    = out + 2 * (size_t)NN * DEMB;        // [8192, 8192]

    static bool attr_set = false;
    if (!attr_set) {
        cudaFuncSetAttribute(dist_mma, cudaFuncAttributeMaxDynamicSharedMemorySize, DSMEM);
        attr_set = true;
    }

    conv_kernel<<<NN, 256>>>(X);
    sq_kernel<<<NN / 8, 256>>>(X);
    dist_mma<<<NTILES, 256, DSMEM>>>();               // upper-tri HMMA -> fp16 D + mirror
    topk_fast<<<NN, 128>>>();                         // R13 threshold filter (best known)
    refine_kernel<<<NN, 768>>>(X);                    // warp-per-candidate exact top-11
    zero_cnt<<<NN / 256, 256>>>();
    count_kernel<<<(NN * TK + 255) / 256, 256>>>();
    dv_kernel<<<NN / 256, 256>>>();
    zero_kernel<<<2048, 256>>>((float4*)H, (size_t)NN * NN / 4);
    scatterH<<<(NN * TK + 255) / 256, 256>>>(H);
    gather_kernel<<<NN, 256>>>(X);
    out_gemm<<<dim3(DEMB / 64, NN / 64), 256>>>(theta, Xout);
    zero_kernel<<<256, 256>>>((float4*)E, (size_t)NN * DEMB / 4);
    scatterE<<<NN, 256>>>(Xout, E);
    scaleE<<<NN * DEMB / 256, 256>>>(E);
}

// round 17
// speedup vs baseline: 1.0832x; 1.0597x over previous
#include <cuda_runtime.h>
#include <cuda_bf16.h>
#include <cuda_fp16.h>
#include <cstdint>
#include <cstddef>

#define NN   8192
#define DF   784
#define DFP  800     // padded K (25 * 32)
#define DEMB 256
#define TK   11
#define TK2  24      // coarse candidate count (margin >> coarse error)
#define NCB  64      // column blocks per row (NN / 128)
#define CAP  512     // survivor buffer capacity
#define NTILES 2080  // upper-triangle 128x128 tiles: 64*65/2

// ---------------- scratch (static device globals; no allocs) ----------------
__device__ float g_sq[NN];                            // correctly-rounded fp32 row norms
__device__ __align__(16) __nv_bfloat16 g_Xb[(size_t)NN * DFP];  // bf16 X, zero-padded
__device__ __align__(16) __half g_D[(size_t)NN * NN]; // fp16 coarse dist (128 MB)
__device__ float g_bmin[(size_t)NN * NCB];            // per-(row, colblock) min (fp16-rounded)
__device__ int   g_idx24[NN * TK2];                   // coarse candidates
__device__ int   g_idx[NN * TK];                      // refined top-11
__device__ int   g_cnt[NN];
__device__ float g_dv[NN];
__device__ float g_G[(size_t)NN * DF];                // gathered dv-weighted rows

__device__ __forceinline__ unsigned smem_u32(const void* p) {
    return (unsigned)__cvta_generic_to_shared(p);
}

// ---------------- 0. convert X -> bf16 (zero-pad K to 800) ----------------
__global__ void conv_kernel(const float* __restrict__ X) {
    int row = blockIdx.x;
    for (int c = threadIdx.x; c < DFP; c += 256) {
        g_Xb[(size_t)row * DFP + c] =
            (c < DF) ? __float2bfloat16_rn(X[(size_t)row * DF + c]) : __float2bfloat16_rn(0.f);
    }
}

// ---------------- 1. row squared norms (correctly rounded) ----------------
__global__ void sq_kernel(const float* __restrict__ X) {
    int row  = blockIdx.x * 8 + (threadIdx.x >> 5);
    int lane = threadIdx.x & 31;
    const float* xr = X + (size_t)row * DF;
    float s = 0.f, c = 0.f;
    for (int k = lane; k < DF; k += 32) {
        float v = xr[k];
        float p = __fmul_rn(v, v);
        float y = __fsub_rn(p, c);
        float t = __fadd_rn(s, y);
        c = __fsub_rn(__fsub_rn(t, s), y);
        s = t;
    }
    double d = (double)s + (double)c;
    #pragma unroll
    for (int o = 16; o; o >>= 1) d += __shfl_xor_sync(0xffffffffu, d, o);
    if (lane == 0) g_sq[row] = (float)d;
}

// ---------------- 2. coarse dist: upper-tri HMMA + fp16 store + mirror + fused H zero ----------------
#define SROW 40           // smem row stride in bf16 elems (80 B, conflict-free ldmatrix)
#define TPAD 129          // transpose tile stride in halfs (odd -> conflict-free)
#define DSMEM (128 * TPAD * 2 > 2 * 128 * SROW * 2 ? 128 * TPAD * 2 : 2 * 128 * SROW * 2)

__global__ __launch_bounds__(256) void dist_mma(float* __restrict__ H) {
    extern __shared__ char dsm[];
    __nv_bfloat16* As = (__nv_bfloat16*)dsm;          // 128*SROW*2 = 10240 B
    __nv_bfloat16* Bs = As + 128 * SROW;              // +10240 B
    __half* tileh = (__half*)dsm;                     // reused for transpose (33024 B)
    __shared__ float swm[128][4];
    __shared__ float scm[128][2];

    // linear block id -> upper-triangle (by, bx), bx >= by
    int t = blockIdx.x;
    int by = (int)(64.5f - sqrtf(64.5f * 64.5f - 2.0f * (float)t));
    while ((by + 1) * 64 - ((by + 1) * by) / 2 <= t) by++;
    while (by * 64 - (by * (by - 1)) / 2 > t) by--;
    int bx = by + (t - (by * 64 - (by * (by - 1)) / 2));

    int tid  = threadIdx.x;
    int warp = tid >> 5, lane = tid & 31;
    int bi = by * 128, bj = bx * 128;
    int wm = (warp >> 2) * 64;     // 0 / 64
    int wn = (warp & 3) * 32;      // 0 / 32 / 64 / 96
    bool offdiag = (bi != bj);

    // fused H zero: this tile's rectangle + mirror (overlaps with MMA below)
    {
        float4 z4 = make_float4(0.f, 0.f, 0.f, 0.f);
        float4* Hq = (float4*)H;
        #pragma unroll
        for (int q = 0; q < 16; q++) {
            int lin = q * 256 + tid;
            int r = lin >> 5, c = lin & 31;
            Hq[(size_t)(bi + r) * (NN / 4) + (bj >> 2) + c] = z4;
        }
        if (offdiag) {
            #pragma unroll
            for (int q = 0; q < 16; q++) {
                int lin = q * 256 + tid;
                int r = lin >> 5, c = lin & 31;
                Hq[(size_t)(bj + r) * (NN / 4) + (bi >> 2) + c] = z4;
            }
        }
    }

    float acc[4][4][4];
    #pragma unroll
    for (int m = 0; m < 4; m++)
        #pragma unroll
        for (int n = 0; n < 4; n++)
            #pragma unroll
            for (int r = 0; r < 4; r++) acc[m][n][r] = 0.f;

    for (int kt = 0; kt < DFP / 32; kt++) {
        #pragma unroll
        for (int l = 0; l < 2; l++) {
            int q = tid + l * 256;
            int row = q >> 2, ch = q & 3;
            const int4* sa = (const int4*)(g_Xb + (size_t)(bi + row) * DFP + kt * 32 + ch * 8);
            *(int4*)(As + row * SROW + ch * 8) = *sa;
            const int4* sb = (const int4*)(g_Xb + (size_t)(bj + row) * DFP + kt * 32 + ch * 8);
            *(int4*)(Bs + row * SROW + ch * 8) = *sb;
        }
        __syncthreads();

        #pragma unroll
        for (int ks = 0; ks < 2; ks++) {
            int k0 = ks * 16;
            uint32_t a[4][4];
            #pragma unroll
            for (int mt = 0; mt < 4; mt++) {
                unsigned ad = smem_u32(As + (wm + mt * 16 + (lane & 15)) * SROW
                                          + k0 + ((lane >> 4) << 3));
                asm volatile("ldmatrix.sync.aligned.m8n8.x4.shared.b16 {%0,%1,%2,%3}, [%4];"
                             : "=r"(a[mt][0]), "=r"(a[mt][1]), "=r"(a[mt][2]), "=r"(a[mt][3])
                             : "r"(ad));
            }
            uint32_t b[4][2];
            #pragma unroll
            for (int bt = 0; bt < 2; bt++) {
                int nloc = wn + bt * 16 + ((lane >> 4) << 3) + (lane & 7);
                unsigned ad = smem_u32(Bs + nloc * SROW + k0 + (((lane >> 3) & 1) << 3));
                uint32_t r0, r1, r2, r3;
                asm volatile("ldmatrix.sync.aligned.m8n8.x4.shared.b16 {%0,%1,%2,%3}, [%4];"
                             : "=r"(r0), "=r"(r1), "=r"(r2), "=r"(r3) : "r"(ad));
                b[2 * bt][0] = r0; b[2 * bt][1] = r1;
                b[2 * bt + 1][0] = r2; b[2 * bt + 1][1] = r3;
            }
            #pragma unroll
            for (int mt = 0; mt < 4; mt++)
                #pragma unroll
                for (int nt = 0; nt < 4; nt++) {
                    asm volatile(
                        "mma.sync.aligned.m16n8k16.row.col.f32.bf16.bf16.f32 "
                        "{%0,%1,%2,%3}, {%4,%5,%6,%7}, {%8,%9}, {%0,%1,%2,%3};"
                        : "+f"(acc[mt][nt][0]), "+f"(acc[mt][nt][1]),
                          "+f"(acc[mt][nt][2]), "+f"(acc[mt][nt][3])
                        : "r"(a[mt][0]), "r"(a[mt][1]), "r"(a[mt][2]), "r"(a[mt][3]),
                          "r"(b[nt][0]), "r"(b[nt][1]));
                }
        }
        __syncthreads();
    }

    // epilogue: fp16 dist store + row-min over fp16-rounded values
    int r_in = lane >> 2, cb = (lane & 3) * 2;
    #pragma unroll
    for (int mt = 0; mt < 4; mt++) {
        #pragma unroll
        for (int half_ = 0; half_ < 2; half_++) {
            int rloc = wm + mt * 16 + r_in + half_ * 8;
            int gi = bi + rloc;
            float sqi = g_sq[gi];
            float rmin = 3.4e38f;
            #pragma unroll
            for (int nt = 0; nt < 4; nt++) {
                int cloc = wn + nt * 8 + cb;
                int gj = bj + cloc;
                float ox = fabsf(sqi + g_sq[gj]     - 2.f * acc[mt][nt][half_ * 2 + 0]);
                float oy = fabsf(sqi + g_sq[gj + 1] - 2.f * acc[mt][nt][half_ * 2 + 1]);
                __half2 h2 = __floats2half2_rn(ox, oy);
                *reinterpret_cast<__half2*>(g_D + (size_t)gi * NN + gj) = h2;
                float lx = __low2float(h2), ly = __high2float(h2);
                acc[mt][nt][half_ * 2 + 0] = lx;
                acc[mt][nt][half_ * 2 + 1] = ly;
                rmin = fminf(rmin, fminf(lx, ly));
            }
            rmin = fminf(rmin, __shfl_xor_sync(0xffffffffu, rmin, 1));
            rmin = fminf(rmin, __shfl_xor_sync(0xffffffffu, rmin, 2));
            if ((lane & 3) == 0)
                swm[rloc][warp & 3] = rmin;
        }
    }

    if (offdiag) {
        // col-min (mirror-row min) over fp16-rounded values
        #pragma unroll
        for (int nt = 0; nt < 4; nt++) {
            float v0 = 3.4e38f, v1 = 3.4e38f;
            #pragma unroll
            for (int mt = 0; mt < 4; mt++) {
                v0 = fminf(v0, fminf(acc[mt][nt][0], acc[mt][nt][2]));
                v1 = fminf(v1, fminf(acc[mt][nt][1], acc[mt][nt][3]));
            }
            #pragma unroll
            for (int o = 4; o <= 16; o <<= 1) {
                v0 = fminf(v0, __shfl_xor_sync(0xffffffffu, v0, o));
                v1 = fminf(v1, __shfl_xor_sync(0xffffffffu, v1, o));
            }
            if (r_in == 0) {
                scm[wn + nt * 8 + cb + 0][wm >> 6] = v0;
                scm[wn + nt * 8 + cb + 1][wm >> 6] = v1;
            }
        }
        // stage tile (half) for transposed mirror store
        #pragma unroll
        for (int mt = 0; mt < 4; mt++)
            #pragma unroll
            for (int half_ = 0; half_ < 2; half_++) {
                int rloc = wm + mt * 16 + r_in + half_ * 8;
                #pragma unroll
                for (int nt = 0; nt < 4; nt++) {
                    int cloc = wn + nt * 8 + cb;
                    tileh[rloc * TPAD + cloc]     = __float2half_rn(acc[mt][nt][half_ * 2 + 0]);
                    tileh[rloc * TPAD + cloc + 1] = __float2half_rn(acc[mt][nt][half_ * 2 + 1]);
                }
            }
    }
    __syncthreads();

    if (tid < 128) {
        float m = fminf(fminf(swm[tid][0], swm[tid][1]),
                        fminf(swm[tid][2], swm[tid][3]));
        g_bmin[(size_t)(bi + tid) * NCB + bx] = m;
        if (offdiag) {
            float c = fminf(scm[tid][0], scm[tid][1]);
            g_bmin[(size_t)(bj + tid) * NCB + by] = c;
        }
    }

    if (offdiag) {
        // mirror store: D[bj + r][bi + 2c2 .. +1] = (tile[2c2][r], tile[2c2+1][r])
        for (int idx = tid; idx < 128 * 64; idx += 256) {
            int r = idx >> 6, c2 = idx & 63;
            __half a = tileh[(2 * c2) * TPAD + r];
            __half b = tileh[(2 * c2 + 1) * TPAD + r];
            *reinterpret_cast<__half2*>(g_D + (size_t)(bj + r) * NN + bi + 2 * c2) =
                __halves2half2(a, b);
        }
    }
}

// ---------------- 3. per-row top-24 via threshold filter (fp16, MLP=8; R13 config) ----------------
__global__ __launch_bounds__(128) void topk_fast() {
    int row = blockIdx.x, t = threadIdx.x;
    __shared__ float sb[NCB];
    __shared__ float sT;
    __shared__ int cnt;
    __shared__ unsigned long long buf[CAP];

    if (t < NCB) sb[t] = g_bmin[(size_t)row * NCB + t];
    if (t == 0) cnt = 0;
    __syncthreads();

    // parallel rank-select: T = 24th smallest block-min
    if (t < NCB) {
        float x = sb[t];
        int r = 0;
        #pragma unroll 16
        for (int j = 0; j < NCB; j++)
            r += (sb[j] < x) || (sb[j] == x && j < t);
        if (r == TK2 - 1) sT = x;
    }
    __syncthreads();
    float T = sT;
    __half2 T2 = __half2half2(__float2half_rn(T));   // T is fp16-representable exactly

    // preload 8 x uint4 (128 B = 64 halfs / thread): MLP=8
    const uint4* dr4 = (const uint4*)(g_D + (size_t)row * NN);
    uint4 w[8];
    #pragma unroll
    for (int i = 0; i < 8; i++) w[i] = dr4[t + i * 128];

    #pragma unroll
    for (int i = 0; i < 8; i++) {
        int base = (t + i * 128) * 8;    // first half index of this uint4
        const __half2* hp = (const __half2*)&w[i];
        #pragma unroll
        for (int q = 0; q < 4; q++) {
            __half2 h = hp[q];
            if (!__hbgt2(h, T2)) {       // at least one lane <= T (rare)
                float fx = __low2float(h), fy = __high2float(h);
                if (fx <= T) {
                    int p = atomicAdd(&cnt, 1);
                    if (p < CAP)
                        buf[p] = ((unsigned long long)__float_as_uint(fx) << 32)
                                 | (unsigned)(base + 2 * q);
                }
                if (fy <= T) {
                    int p = atomicAdd(&cnt, 1);
                    if (p < CAP)
                        buf[p] = ((unsigned long long)__float_as_uint(fy) << 32)
                                 | (unsigned)(base + 2 * q + 1);
                }
            }
        }
    }
    __syncthreads();

    if (t == 0) {
        unsigned long long best[TK2];
        #pragma unroll
        for (int k = 0; k < TK2; k++) best[k] = ~0ull;
        if (cnt <= CAP) {
            int n = cnt;
            for (int i = 0; i < n; i++) {
                unsigned long long x = buf[i];
                if (x < best[TK2 - 1]) {
                    int k = TK2 - 1;
                    while (k > 0 && best[k - 1] > x) { best[k] = best[k - 1]; k--; }
                    best[k] = x;
                }
            }
        } else {
            // fallback (practically unreachable): full serial scan of fp16 row
            const __half* drh = g_D + (size_t)row * NN;
            for (int j = 0; j < NN; j++) {
                float d = __half2float(drh[j]);
                unsigned long long x =
                    ((unsigned long long)__float_as_uint(d) << 32) | (unsigned)j;
                if (x < best[TK2 - 1]) {
                    int k = TK2 - 1;
                    while (k > 0 && best[k - 1] > x) { best[k] = best[k - 1]; k--; }
                    best[k] = x;
                }
            }
        }
        #pragma unroll
        for (int k = 0; k < TK2; k++) g_idx24[row * TK2 + k] = (int)(unsigned)best[k];
    }
}

// ---------------- 4. refine: exact dists with ref's rounding chain (R13 config) ----------------
__global__ __launch_bounds__(128) void refine_kernel(const float* __restrict__ X) {
    int row = blockIdx.x;
    int wid = threadIdx.x >> 5, lane = threadIdx.x & 31;
    __shared__ unsigned long long keys[TK2];
    __shared__ int cand[TK2];
    if (threadIdx.x < TK2) cand[threadIdx.x] = g_idx24[row * TK2 + threadIdx.x];
    __syncthreads();

    float sqi = g_sq[row];
    const float* xi = X + (size_t)row * DF;

    for (int k4 = wid; k4 < TK2; k4 += 4) {
        int j = cand[k4];
        const float* xj = X + (size_t)j * DF;
        float s = 0.f, c = 0.f;
        for (int k = lane; k < DF; k += 32) {
            float p = __fmul_rn(xi[k], xj[k]);
            float y = __fsub_rn(p, c);
            float t = __fadd_rn(s, y);
            c = __fsub_rn(__fsub_rn(t, s), y);
            s = t;
        }
        double d = (double)s + (double)c;
        #pragma unroll
        for (int o = 16; o; o >>= 1) d += __shfl_xor_sync(0xffffffffu, d, o);
        if (lane == 0) {
            float dotf = (float)d;
            float t1 = __fadd_rn(sqi, g_sq[j]);
            float t3 = fabsf(__fsub_rn(t1, __fmul_rn(2.0f, dotf)));
            keys[k4] = ((unsigned long long)__float_as_uint(t3) << 32) | (unsigned)j;
        }
    }
    __syncthreads();

    if (threadIdx.x == 0) {
        unsigned long long a[TK2];
        #pragma unroll
        for (int i = 0; i < TK2; i++) a[i] = keys[i];
        #pragma unroll
        for (int i = 1; i < TK2; i++) {
            unsigned long long v = a[i];
            int k = i - 1;
            while (k >= 0 && a[k] > v) { a[k + 1] = a[k]; k--; }
            a[k + 1] = v;
        }
        #pragma unroll
        for (int k = 0; k < TK; k++) g_idx[row * TK + k] = (int)(unsigned)a[k];
    }
}

// ---------------- 5. vertex degrees ----------------
__global__ void zero_cnt() {
    int t = blockIdx.x * 256 + threadIdx.x;
    if (t < NN) g_cnt[t] = 0;
}
__global__ void count_kernel() {
    int t = blockIdx.x * 256 + threadIdx.x;
    if (t < NN * TK) atomicAdd(&g_cnt[g_idx[t]], 1);
}
__global__ void dv_kernel() {
    int t = blockIdx.x * 256 + threadIdx.x;
    if (t < NN) g_dv[t] = 1.0f / sqrtf((float)g_cnt[t]);
}

// ---------------- zero fill ----------------
__global__ void zero_kernel(float4* __restrict__ p, size_t n4) {
    size_t t = (size_t)blockIdx.x * blockDim.x + threadIdx.x;
    size_t stride = (size_t)gridDim.x * blockDim.x;
    float4 z = make_float4(0.f, 0.f, 0.f, 0.f);
    for (size_t i = t; i < n4; i += stride) p[i] = z;
}

// ---------------- 6. H scatter: H[idx[i][k]][i] = 1 ----------------
__global__ void scatterH(float* __restrict__ H) {
    int t = blockIdx.x * 256 + threadIdx.x;
    if (t < NN * TK) {
        int i = t / TK;
        int r = g_idx[t];
        H[(size_t)r * NN + i] = 1.0f;
    }
}

// ---------------- 7. gather: G[i] = sum_k dv[idx]*X[idx] ----------------
__global__ __launch_bounds__(256) void gather_kernel(const float* __restrict__ X) {
    int i = blockIdx.x;
    __shared__ int   sidx[TK];
    __shared__ float sdv[TK];
    if (threadIdx.x < TK) {
        int r = g_idx[i * TK + threadIdx.x];
        sidx[threadIdx.x] = r;
        sdv[threadIdx.x]  = g_dv[r];
    }
    __syncthreads();
    for (int c = threadIdx.x; c < DF; c += 256) {
        float s = 0.f;
        #pragma unroll
        for (int k = 0; k < TK; k++)
            s = fmaf(sdv[k], X[(size_t)sidx[k] * DF + c], s);
        g_G[(size_t)i * DF + c] = s;
    }
}

// ---------------- 8. X_out = de * G @ theta   (M=8192, N=256, K=784) ----------------
#define BK 16
#define SPAD 4
__global__ __launch_bounds__(256) void out_gemm(const float* __restrict__ theta,
                                                float* __restrict__ Xout) {
    __shared__ float As[BK][64 + SPAD];
    __shared__ float Bs[BK][64 + SPAD];
    int tid = threadIdx.x;
    int tx = tid & 15, ty = tid >> 4;
    int bi = blockIdx.y * 64, bj = blockIdx.x * 64;

    float acc[4][4];
    #pragma unroll
    for (int m = 0; m < 4; m++)
        #pragma unroll
        for (int n = 0; n < 4; n++) acc[m][n] = 0.f;

    for (int k0 = 0; k0 < DF; k0 += BK) {
        {
            int row = tid >> 2, c4 = (tid & 3) * 4;
            float4 v = *reinterpret_cast<const float4*>(g_G + (size_t)(bi + row) * DF + k0 + c4);
            As[c4 + 0][row] = v.x; As[c4 + 1][row] = v.y;
            As[c4 + 2][row] = v.z; As[c4 + 3][row] = v.w;
            int kr = tid >> 4, n4 = (tid & 15) * 4;
            float4 w = *reinterpret_cast<const float4*>(theta + (size_t)(k0 + kr) * DEMB + bj + n4);
            Bs[kr][n4 + 0] = w.x; Bs[kr][n4 + 1] = w.y;
            Bs[kr][n4 + 2] = w.z; Bs[kr][n4 + 3] = w.w;
        }
        __syncthreads();
        #pragma unroll
        for (int kk = 0; kk < BK; kk++) {
            float a[4], b[4];
            #pragma unroll
            for (int m = 0; m < 4; m++) a[m] = As[kk][ty * 4 + m];
            #pragma unroll
            for (int n = 0; n < 4; n++) b[n] = Bs[kk][tx * 4 + n];
            #pragma unroll
            for (int m = 0; m < 4; m++)
                #pragma unroll
                for (int n = 0; n < 4; n++) acc[m][n] = fmaf(a[m], b[n], acc[m][n]);
        }
        __syncthreads();
    }
    const float de = 0.30151134457776363f;  // 11^-0.5
    #pragma unroll
    for (int m = 0; m < 4; m++) {
        int i = bi + ty * 4 + m;
        float4 o;
        o.x = de * acc[m][0]; o.y = de * acc[m][1];
        o.z = de * acc[m][2]; o.w = de * acc[m][3];
        *reinterpret_cast<float4*>(Xout + (size_t)i * DEMB + bj + tx * 4) = o;
    }
}

// ---------------- 9. E = dv * de * scatter-add of X_out ----------------
__global__ void scatterE(const float* __restrict__ Xout, float* __restrict__ E) {
    int j = blockIdx.x;
    int c = threadIdx.x;
    float v = Xout[(size_t)j * DEMB + c];
    #pragma unroll
    for (int k = 0; k < TK; k++) {
        int r = __ldg(&g_idx[j * TK + k]);
        atomicAdd(E + (size_t)r * DEMB + c, v);
    }
}
__global__ void scaleE(float* __restrict__ E) {
    int t = blockIdx.x * 256 + threadIdx.x;
    const float de = 0.30151134457776363f;
    int i = t >> 8;
    E[t] *= g_dv[i] * de;
}

// ---------------- launch ----------------
extern "C" void kernel_launch(void* const* d_in, const int* in_sizes, int n_in,
                              void* d_out, int out_size) {
    const float* X     = (const float*)d_in[0];
    const float* theta = (const float*)d_in[1];
    float* out  = (float*)d_out;
    float* Xout = out;                                // [8192, 256]
    float* E    = out + (size_t)NN * DEMB;            // [8192, 256]
    float* H    = out + 2 * (size_t)NN * DEMB;        // [8192, 8192]

    static bool attr_set = false;
    if (!attr_set) {
        cudaFuncSetAttribute(dist_mma, cudaFuncAttributeMaxDynamicSharedMemorySize, DSMEM);
        attr_set = true;
    }

    conv_kernel<<<NN, 256>>>(X);
    sq_kernel<<<NN / 8, 256>>>(X);
    dist_mma<<<NTILES, 256, DSMEM>>>(H);              // upper-tri HMMA + fp16 D + H zeros
    topk_fast<<<NN, 128>>>();                         // R13 threshold filter (best known)
    refine_kernel<<<NN, 128>>>(X);                    // R13 exact-emulated top-11
    zero_cnt<<<NN / 256, 256>>>();
    count_kernel<<<(NN * TK + 255) / 256, 256>>>();
    dv_kernel<<<NN / 256, 256>>>();
    scatterH<<<(NN * TK + 255) / 256, 256>>>(H);
    gather_kernel<<<NN, 256>>>(X);
    out_gemm<<<dim3(DEMB / 64, NN / 64), 256>>>(theta, Xout);
    zero_kernel<<<256, 256>>>((float4*)E, (size_t)NN * DEMB / 4);
    scatterE<<<NN, 256>>>(Xout, E);
    scaleE<<<NN * DEMB / 256, 256>>>(E);
}